// round 7
// baseline (speedup 1.0000x reference)
#include <cuda_runtime.h>
#include <stdint.h>
#include <math.h>

#define THREADS 128
#define CPT 32                          // cells per tile
#define STAGES 3
#define NB 4096
#define TOTAL_CELLS (NB * 14 * 14)      // 802816
#define NTILES (TOTAL_CELLS / CPT)      // 25088
#define BLOCKS_PER_SM 9
#define GRID (148 * BLOCKS_PER_SM)      // 1332 persistent blocks
#define TILE_FLOATS (CPT * 30)          // 960 floats per array
#define TILE_F4 (TILE_FLOATS / 4)       // 240

__device__ double g_acc = 0.0;
__device__ unsigned int g_ticket = 0u;

__device__ __forceinline__ void cp16(uint32_t s, const float4* g) {
    asm volatile("cp.async.cg.shared.global [%0], [%1], 16;" :: "r"(s), "l"(g));
}
__device__ __forceinline__ void cp_commit() {
    asm volatile("cp.async.commit_group;" ::: "memory");
}

__global__ void __launch_bounds__(THREADS, BLOCKS_PER_SM)
yolo_loss_kernel(const float* __restrict__ pred, const float* __restrict__ target,
                 float* __restrict__ out) {
    __shared__ float sp[STAGES][TILE_FLOATS];
    __shared__ float st[STAGES][TILE_FLOATS];
    __shared__ float wsum[THREADS / 32];

    const int tid = threadIdx.x;
    const uint32_t sp0 = (uint32_t)__cvta_generic_to_shared(&sp[0][0]);
    const uint32_t st0 = (uint32_t)__cvta_generic_to_shared(&st[0][0]);
    const uint32_t stage_bytes = (uint32_t)(TILE_FLOATS * 4);

    // issue one tile's loads into stage `buf`; 240 float4 per array, 128 threads
    auto issue = [&](int tile, int buf) {
        const float4* gp = (const float4*)pred + (size_t)tile * TILE_F4;
        const float4* gt = (const float4*)target + (size_t)tile * TILE_F4;
        const uint32_t dp = sp0 + (uint32_t)buf * stage_bytes;
        const uint32_t dt = st0 + (uint32_t)buf * stage_bytes;
        // stride 0: all threads would exceed 240 at k=1, so: 240 = 128 + 112
        cp16(dp + tid * 16, gp + tid);
        cp16(dt + tid * 16, gt + tid);
        if (tid < TILE_F4 - THREADS) {   // tid < 112
            const int i = THREADS + tid;
            cp16(dp + i * 16, gp + i);
            cp16(dt + i * 16, gt + i);
        }
    };

    // ---- prologue: tiles t0, t1 in flight ----
    const int bid = blockIdx.x;
    int t = bid;
    issue(t, 0);
    cp_commit();
    if (t + GRID < NTILES) issue(t + GRID, 1);
    cp_commit();                          // uniform group accounting (may be empty)

    // compute assignment: lanes 0-7 of each warp, cell = wid*8 + lane
    const int lane = tid & 31;
    const int wid = tid >> 5;
    const bool active = (lane < 8);
    const int cell = wid * 8 + lane;      // 0..31

    float acc = 0.0f;
    int b = 0;
    while (t < NTILES) {
        asm volatile("cp.async.wait_group 1;" ::: "memory");   // tile t arrived
        __syncthreads();                  // single barrier per round

        // issue tile t+2 into stage b+2 (== b-1, consumed before this barrier)
        {
            const int t2 = t + 2 * GRID;
            int b2 = b + 2; if (b2 >= STAGES) b2 -= STAGES;
            if (t2 < NTILES) issue(t2, b2);
            cp_commit();
        }

        // ---- per-cell loss from stage b ----
        if (active) {
            const float* p  = &sp[b][cell * 30];
            const float* tt = &st[b][cell * 30];

            const float t4 = tt[4];
            const float objm   = (t4 > 0.0f) ? 1.0f : 0.0f;
            const float noobjm = (t4 == 0.0f) ? 1.0f : 0.0f;

            const float d4 = p[4] - t4;
            const float d9 = p[9] - tt[9];
            const float l_noobj = d4 * d4 + d9 * d9;

            const float inv_s = 1.0f / 14.0f;
            const float txc = tt[0] * inv_s, tyc = tt[1] * inv_s;
            const float thw = 0.5f * tt[2], thh = 0.5f * tt[3];
            const float tx0 = txc - thw, ty0 = tyc - thh;
            const float tx1 = txc + thw, ty1 = tyc + thh;
            const float area_t = (tx1 - tx0) * (ty1 - ty0);

            float iou[2];
            #pragma unroll
            for (int bb = 0; bb < 2; bb++) {
                const float* pb = p + 5 * bb;
                const float pxc = pb[0] * inv_s, pyc = pb[1] * inv_s;
                const float phw = 0.5f * pb[2], phh = 0.5f * pb[3];
                const float px0 = pxc - phw, py0 = pyc - phh;
                const float px1 = pxc + phw, py1 = pyc + phh;
                const float area_p = (px1 - px0) * (py1 - py0);
                const float iw = fmaxf(fminf(px1, tx1) - fmaxf(px0, tx0), 0.0f);
                const float ih = fmaxf(fminf(py1, ty1) - fmaxf(py0, ty0), 0.0f);
                const float inter = iw * ih;
                iou[bb] = inter / (area_p + area_t - inter);
            }

            // responsible box: first-max on tie (jnp.argmax semantics)
            const int roff = (iou[1] > iou[0]) ? 5 : 0;
            const float max_iou = fmaxf(iou[0], iou[1]);

            const float* pr = p + roff;
            const float* tr = tt + roff;

            const float dx = pr[0] - tr[0];
            const float dy = pr[1] - tr[1];
            const float l_xy = dx * dx + dy * dy;

            const float dw = sqrtf(pr[2]) - sqrtf(tr[2]);
            const float dh = sqrtf(pr[3]) - sqrtf(tr[3]);
            const float l_wh = dw * dw + dh * dh;

            const float dob = pr[4] - max_iou;
            const float l_obj = dob * dob;

            float l_cls = 0.0f;
            #pragma unroll
            for (int c = 0; c < 20; c++) {
                const float dc = p[10 + c] - tt[10 + c];
                l_cls = fmaf(dc, dc, l_cls);
            }

            acc += objm * (5.0f * (l_xy + l_wh) + l_obj + l_cls)
                 + 0.5f * noobjm * l_noobj;
        }

        b += 1; if (b >= STAGES) b = 0;
        t += GRID;
    }

    // ---- block reduction + global accumulate ----
    float v = acc;
    #pragma unroll
    for (int o = 16; o > 0; o >>= 1) v += __shfl_down_sync(0xFFFFFFFFu, v, o);
    if (lane == 0) wsum[wid] = v;
    __syncthreads();

    if (tid == 0) {
        const float s = wsum[0] + wsum[1] + wsum[2] + wsum[3];
        atomicAdd(&g_acc, (double)s);
        __threadfence();
        const unsigned int ticket = atomicAdd(&g_ticket, 1u);
        if (ticket == (unsigned int)(GRID - 1)) {
            const double total = g_acc;
            out[0] = (float)(total * (1.0 / (double)NB));
            g_acc = 0.0;                   // reset for next graph replay
            __threadfence();
            g_ticket = 0u;
        }
    }
}

extern "C" void kernel_launch(void* const* d_in, const int* in_sizes, int n_in,
                              void* d_out, int out_size) {
    const float* pred = (const float*)d_in[0];
    const float* target = (const float*)d_in[1];
    float* out = (float*)d_out;
    yolo_loss_kernel<<<GRID, THREADS>>>(pred, target, out);
}

// round 8
// speedup vs baseline: 1.1170x; 1.1170x over previous
#include <cuda_runtime.h>
#include <stdint.h>
#include <math.h>

#define THREADS 128
#define CPT 64                          // cells per tile
#define STAGES 3
#define NB 4096
#define TOTAL_CELLS (NB * 14 * 14)      // 802816
#define NTILES (TOTAL_CELLS / CPT)      // 12544
#define BLOCKS_PER_SM 4
#define GRID (148 * BLOCKS_PER_SM)      // 592 persistent blocks
#define TILE_FLOATS (CPT * 30)          // 1920 floats
#define TILE_BYTES (TILE_FLOATS * 4)    // 7680 B per array per tile

__device__ double g_acc = 0.0;
__device__ unsigned int g_ticket = 0u;

__device__ __forceinline__ void cp_bulk(uint32_t dst, const float* src,
                                        uint32_t bytes, uint32_t mb) {
    asm volatile(
        "cp.async.bulk.shared::cta.global.mbarrier::complete_tx::bytes [%0], [%1], %2, [%3];"
        :: "r"(dst), "l"(src), "r"(bytes), "r"(mb) : "memory");
}

__device__ __forceinline__ void mbar_init(uint32_t mb, uint32_t count) {
    asm volatile("mbarrier.init.shared.b64 [%0], %1;" :: "r"(mb), "r"(count) : "memory");
}

__device__ __forceinline__ void mbar_expect_tx(uint32_t mb, uint32_t bytes) {
    asm volatile("mbarrier.arrive.expect_tx.shared.b64 _, [%0], %1;"
                 :: "r"(mb), "r"(bytes) : "memory");
}

__device__ __forceinline__ void mbar_wait(uint32_t mb, uint32_t parity) {
    uint32_t done;
    asm volatile(
        "{\n\t"
        ".reg .pred p;\n\t"
        "mbarrier.try_wait.parity.acquire.cta.shared::cta.b64 p, [%1], %2;\n\t"
        "selp.b32 %0, 1, 0, p;\n\t"
        "}" : "=r"(done) : "r"(mb), "r"(parity) : "memory");
    if (!done) {
        asm volatile(
            "{\n\t"
            ".reg .pred P1;\n\t"
            "WAIT_LOOP_%=:\n\t"
            "mbarrier.try_wait.parity.acquire.cta.shared::cta.b64 P1, [%0], %1, 0x989680;\n\t"
            "@P1 bra.uni WAIT_DONE_%=;\n\t"
            "bra.uni WAIT_LOOP_%=;\n\t"
            "WAIT_DONE_%=:\n\t"
            "}" :: "r"(mb), "r"(parity) : "memory");
    }
}

__global__ void __launch_bounds__(THREADS, BLOCKS_PER_SM)
yolo_loss_kernel(const float* __restrict__ pred, const float* __restrict__ target,
                 float* __restrict__ out) {
    __shared__ __align__(16) float sp[STAGES][TILE_FLOATS];
    __shared__ __align__(16) float st[STAGES][TILE_FLOATS];
    __shared__ __align__(8) uint64_t mbar[STAGES];
    __shared__ float wsum[THREADS / 32];

    const int tid = threadIdx.x;
    const uint32_t sp0 = (uint32_t)__cvta_generic_to_shared(&sp[0][0]);
    const uint32_t st0 = (uint32_t)__cvta_generic_to_shared(&st[0][0]);
    const uint32_t mb0 = (uint32_t)__cvta_generic_to_shared(&mbar[0]);

    if (tid == 0) {
        #pragma unroll
        for (int s = 0; s < STAGES; s++) mbar_init(mb0 + 8u * s, 1u);
        // make init visible to the async (TMA) proxy before first bulk copy
        asm volatile("fence.proxy.async.shared::cta;" ::: "memory");
    }
    __syncthreads();

    // arm stage s with tile `tile` (expect both arrays, then 2 bulk copies)
    auto issue = [&](int tile, int s) {
        const uint32_t mb = mb0 + 8u * s;
        mbar_expect_tx(mb, 2u * TILE_BYTES);
        cp_bulk(sp0 + (uint32_t)s * TILE_BYTES, pred + (size_t)tile * TILE_FLOATS,
                TILE_BYTES, mb);
        cp_bulk(st0 + (uint32_t)s * TILE_BYTES, target + (size_t)tile * TILE_FLOATS,
                TILE_BYTES, mb);
    };

    int t = blockIdx.x;
    if (tid == 0) {
        issue(t, 0);
        if (t + GRID < NTILES) issue(t + GRID, 1);
    }

    float acc = 0.0f;
    int b = 0;
    uint32_t ph = 0;
    while (t < NTILES) {
        mbar_wait(mb0 + 8u * b, ph);        // tile t resident in stage b (acquire)

        // producer: arm stage b+2 with tile t+2*GRID. Safe: stage b+2 was
        // consumed in round t-1's predecessor and all threads passed the
        // end-of-round barrier since then.
        if (tid == 0) {
            const int t2 = t + 2 * GRID;
            if (t2 < NTILES) {
                int b2 = b + 2; if (b2 >= STAGES) b2 -= STAGES;
                issue(t2, b2);
            }
        }

        // ---- per-cell loss from stage b (threads 0..63) ----
        if (tid < CPT) {
            const float* p  = &sp[b][tid * 30];
            const float* tt = &st[b][tid * 30];

            const float t4 = tt[4];
            const float objm   = (t4 > 0.0f) ? 1.0f : 0.0f;
            const float noobjm = (t4 == 0.0f) ? 1.0f : 0.0f;

            const float d4 = p[4] - t4;
            const float d9 = p[9] - tt[9];
            const float l_noobj = d4 * d4 + d9 * d9;

            const float inv_s = 1.0f / 14.0f;
            const float txc = tt[0] * inv_s, tyc = tt[1] * inv_s;
            const float thw = 0.5f * tt[2], thh = 0.5f * tt[3];
            const float tx0 = txc - thw, ty0 = tyc - thh;
            const float tx1 = txc + thw, ty1 = tyc + thh;
            const float area_t = (tx1 - tx0) * (ty1 - ty0);

            float iou[2];
            #pragma unroll
            for (int bb = 0; bb < 2; bb++) {
                const float* pb = p + 5 * bb;
                const float pxc = pb[0] * inv_s, pyc = pb[1] * inv_s;
                const float phw = 0.5f * pb[2], phh = 0.5f * pb[3];
                const float px0 = pxc - phw, py0 = pyc - phh;
                const float px1 = pxc + phw, py1 = pyc + phh;
                const float area_p = (px1 - px0) * (py1 - py0);
                const float iw = fmaxf(fminf(px1, tx1) - fmaxf(px0, tx0), 0.0f);
                const float ih = fmaxf(fminf(py1, ty1) - fmaxf(py0, ty0), 0.0f);
                const float inter = iw * ih;
                iou[bb] = inter / (area_p + area_t - inter);
            }

            // responsible box: first-max on tie (jnp.argmax semantics)
            const int roff = (iou[1] > iou[0]) ? 5 : 0;
            const float max_iou = fmaxf(iou[0], iou[1]);

            const float* pr = p + roff;
            const float* tr = tt + roff;

            const float dx = pr[0] - tr[0];
            const float dy = pr[1] - tr[1];
            const float l_xy = dx * dx + dy * dy;

            const float dw = sqrtf(pr[2]) - sqrtf(tr[2]);
            const float dh = sqrtf(pr[3]) - sqrtf(tr[3]);
            const float l_wh = dw * dw + dh * dh;

            const float dob = pr[4] - max_iou;
            const float l_obj = dob * dob;

            float l_cls = 0.0f;
            #pragma unroll
            for (int c = 0; c < 20; c++) {
                const float dc = p[10 + c] - tt[10 + c];
                l_cls = fmaf(dc, dc, l_cls);
            }

            acc += objm * (5.0f * (l_xy + l_wh) + l_obj + l_cls)
                 + 0.5f * noobjm * l_noobj;
        }

        __syncthreads();                   // bound intra-block skew to one round
        b += 1; if (b >= STAGES) { b = 0; ph ^= 1u; }
        t += GRID;
    }

    // ---- block reduction + global accumulate ----
    float v = acc;
    #pragma unroll
    for (int o = 16; o > 0; o >>= 1) v += __shfl_down_sync(0xFFFFFFFFu, v, o);
    if ((tid & 31) == 0) wsum[tid >> 5] = v;
    __syncthreads();

    if (tid == 0) {
        const float s = wsum[0] + wsum[1] + wsum[2] + wsum[3];
        atomicAdd(&g_acc, (double)s);
        __threadfence();
        const unsigned int ticket = atomicAdd(&g_ticket, 1u);
        if (ticket == (unsigned int)(GRID - 1)) {
            const double total = g_acc;
            out[0] = (float)(total * (1.0 / (double)NB));
            g_acc = 0.0;                   // reset for next graph replay
            __threadfence();
            g_ticket = 0u;
        }
    }
}

extern "C" void kernel_launch(void* const* d_in, const int* in_sizes, int n_in,
                              void* d_out, int out_size) {
    const float* pred = (const float*)d_in[0];
    const float* target = (const float*)d_in[1];
    float* out = (float*)d_out;
    yolo_loss_kernel<<<GRID, THREADS>>>(pred, target, out);
}